// round 7
// baseline (speedup 1.0000x reference)
#include <cuda_runtime.h>
#include <cstdint>

#define BB 64
#define MM 2048
#define DD 512
#define TOTAL_ROWS (BB * MM)              // 131072
#define TICKET_ROWS 8
#define NT (TOTAL_ROWS / TICKET_ROWS)     // 16384 tickets (256 per batch)
#define GRID_BLOCKS (148 * 3)             // 444
#define WARPS_TOTAL (GRID_BLOCKS * 8)     // 3552

// Per-batch best: high 32 = float bits of squared distance (non-negative ->
// monotone bit pattern), low 32 = (MM-1-idx) so ties pick the SMALLEST index
// under atomicMax (matches jnp.argmax first-occurrence). All state zero-init
// at module load and self-reset at kernel end so graph replays start clean.
__device__ unsigned long long g_best[BB];
__device__ int g_cnt[BB];
__device__ int g_ticket;
__device__ int g_exhaust;

__device__ __forceinline__ int fetch_ticket(int lane) {
    int t = 0;
    if (lane == 0) t = atomicAdd(&g_ticket, 1);
    return __shfl_sync(0xFFFFFFFFu, t, 0);
}

__device__ __forceinline__ void flush_batch(
    int b, float best, int bestm, int nrows, int lane,
    const float* __restrict__ buffer, float* __restrict__ out)
{
    unsigned long long packed =
        ((unsigned long long)__float_as_uint(best) << 32) |
        (unsigned int)(MM - 1 - bestm);
    int fin = 0;
    if (lane == 0) {
        atomicMax(&g_best[b], packed);
        __threadfence();                       // max visible before count
        int old = atomicAdd(&g_cnt[b], nrows);
        fin = (old + nrows == MM);
    }
    fin = __shfl_sync(0xFFFFFFFFu, fin, 0);
    if (fin) {
        unsigned long long win = 0ULL;
        if (lane == 0) {
            __threadfence();                   // acquire all maxes
            win = g_best[b];
        }
        win = __shfl_sync(0xFFFFFFFFu, win, 0);
        const int idx = MM - 1 - (int)(unsigned int)(win & 0xFFFFFFFFu);
        const float4* src = reinterpret_cast<const float4*>(
            buffer + ((size_t)b * MM + (size_t)idx) * DD);
        float4* dst = reinterpret_cast<float4*>(out + (size_t)b * DD);
#pragma unroll
        for (int i = 0; i < 4; i++)
            dst[lane + i * 32] = src[lane + i * 32];
        if (lane == 0) {                       // reset batch state for replay
            g_best[b] = 0ULL;
            __threadfence();
            g_cnt[b] = 0;
        }
    }
}

__global__ __launch_bounds__(256, 3) void knn_steal_kernel(
    const float* __restrict__ inputs,   // [BB, DD]
    const float* __restrict__ buffer,   // [BB, MM, DD]
    float* __restrict__ out)            // [BB, DD]
{
    const int lane = threadIdx.x & 31;

    int t = fetch_ticket(lane);
    if (t < NT) {
        int r    = t * TICKET_ROWS;            // current (prefetched) row
        int left = TICKET_ROWS;                // rows remaining in ticket
        int b    = r >> 11;                    // / MM

        const float4* qp = reinterpret_cast<const float4*>(inputs + (size_t)b * DD);
        float4 q0 = qp[lane], q1 = qp[lane + 32], q2 = qp[lane + 64], q3 = qp[lane + 96];

        const float4* rp = reinterpret_cast<const float4*>(buffer + (size_t)r * DD);
        float4 v0 = __ldg(rp + lane),      v1 = __ldg(rp + lane + 32),
               v2 = __ldg(rp + lane + 64), v3 = __ldg(rp + lane + 96);

        float best  = -1.0f;
        int   bestm = 0;
        int   nrows = 0;

        for (;;) {
            // Pick the next row: within ticket, or grab a new ticket.
            int  nr = 0, nleft = 0;
            bool have_next;
            if (left > 1) {
                nr = r + 1; nleft = left - 1; have_next = true;
            } else {
                int t2 = fetch_ticket(lane);
                have_next = (t2 < NT);
                if (have_next) { nr = t2 * TICKET_ROWS; nleft = TICKET_ROWS; }
            }

            // Prefetch next row while this row's FMA + shuffle chain runs.
            float4 n0, n1, n2, n3;
            if (have_next) {
                const float4* np = reinterpret_cast<const float4*>(buffer + (size_t)nr * DD);
                n0 = __ldg(np + lane);      n1 = __ldg(np + lane + 32);
                n2 = __ldg(np + lane + 64); n3 = __ldg(np + lane + 96);
            }

            float acc = 0.0f;
            {
                float dx = v0.x - q0.x, dy = v0.y - q0.y, dz = v0.z - q0.z, dw = v0.w - q0.w;
                acc = fmaf(dx, dx, acc); acc = fmaf(dy, dy, acc);
                acc = fmaf(dz, dz, acc); acc = fmaf(dw, dw, acc);
                dx = v1.x - q1.x; dy = v1.y - q1.y; dz = v1.z - q1.z; dw = v1.w - q1.w;
                acc = fmaf(dx, dx, acc); acc = fmaf(dy, dy, acc);
                acc = fmaf(dz, dz, acc); acc = fmaf(dw, dw, acc);
                dx = v2.x - q2.x; dy = v2.y - q2.y; dz = v2.z - q2.z; dw = v2.w - q2.w;
                acc = fmaf(dx, dx, acc); acc = fmaf(dy, dy, acc);
                acc = fmaf(dz, dz, acc); acc = fmaf(dw, dw, acc);
                dx = v3.x - q3.x; dy = v3.y - q3.y; dz = v3.z - q3.z; dw = v3.w - q3.w;
                acc = fmaf(dx, dx, acc); acc = fmaf(dy, dy, acc);
                acc = fmaf(dz, dz, acc); acc = fmaf(dw, dw, acc);
            }
#pragma unroll
            for (int o = 16; o > 0; o >>= 1)
                acc += __shfl_xor_sync(0xFFFFFFFFu, acc, o);

            const int m = r & (MM - 1);
            if (acc > best) { best = acc; bestm = m; }
            nrows++;

            if (!have_next) {
                flush_batch(b, best, bestm, nrows, lane, buffer, out);
                break;
            }
            const int nb = nr >> 11;
            if (nb != b) {
                flush_batch(b, best, bestm, nrows, lane, buffer, out);
                b = nb;
                qp = reinterpret_cast<const float4*>(inputs + (size_t)b * DD);
                q0 = qp[lane]; q1 = qp[lane + 32]; q2 = qp[lane + 64]; q3 = qp[lane + 96];
                best = -1.0f; bestm = 0; nrows = 0;
            }
            r = nr; left = nleft;
            v0 = n0; v1 = n1; v2 = n2; v3 = n3;
        }
    }

    // Every warp passes exactly once: last one resets ticket state for the
    // next graph replay (kernel-boundary ordering makes this safe).
    if (lane == 0) {
        int old = atomicAdd(&g_exhaust, 1);
        if (old == WARPS_TOTAL - 1) {
            g_ticket  = 0;
            g_exhaust = 0;
        }
    }
}

extern "C" void kernel_launch(void* const* d_in, const int* in_sizes, int n_in,
                              void* d_out, int out_size)
{
    const float* inputs;
    const float* buffer;
    // inputs has BB*DD = 32768 elems, buffer has BB*MM*DD = 67108864.
    if (in_sizes[0] == BB * DD) {
        inputs = (const float*)d_in[0];
        buffer = (const float*)d_in[1];
    } else {
        inputs = (const float*)d_in[1];
        buffer = (const float*)d_in[0];
    }
    float* out = (float*)d_out;

    knn_steal_kernel<<<GRID_BLOCKS, 256>>>(inputs, buffer, out);
}

// round 9
// speedup vs baseline: 1.1889x; 1.1889x over previous
#include <cuda_runtime.h>
#include <cstdint>

#define BB 64
#define MM 2048
#define DD 512
#define TOTAL_ROWS (BB * MM)            // 131072
#define GRID_BLOCKS (148 * 3)           // 444 (one full wave at 3 blocks/SM)
#define WARPS_TOTAL (GRID_BLOCKS * 8)   // 3552 -> ~37 rows/warp

// Per-batch best: high 32 = float bits of squared distance (non-negative ->
// monotone bit pattern), low 32 = (MM-1-idx) so ties pick the SMALLEST index
// under atomicMax (matches jnp.argmax first-occurrence). Zero-init at load;
// the finishing warp resets after the gather so graph replays start clean.
__device__ unsigned long long g_best[BB];
__device__ int g_cnt[BB];

__device__ __forceinline__ void flush_batch(
    int b, float best, int bestm, int nrows, int lane,
    const float* __restrict__ buffer, float* __restrict__ out)
{
    unsigned long long packed =
        ((unsigned long long)__float_as_uint(best) << 32) |
        (unsigned int)(MM - 1 - bestm);
    int fin = 0;
    if (lane == 0) {
        atomicMax(&g_best[b], packed);
        __threadfence();                       // max visible before count
        int old = atomicAdd(&g_cnt[b], nrows);
        fin = (old + nrows == MM);
    }
    fin = __shfl_sync(0xFFFFFFFFu, fin, 0);
    if (fin) {
        unsigned long long win = 0ULL;
        if (lane == 0) {
            __threadfence();                   // acquire all maxes
            win = g_best[b];
        }
        win = __shfl_sync(0xFFFFFFFFu, win, 0);
        const int idx = MM - 1 - (int)(unsigned int)(win & 0xFFFFFFFFu);
        const float4* src = reinterpret_cast<const float4*>(
            buffer + ((size_t)b * MM + (size_t)idx) * DD);
        float4* dst = reinterpret_cast<float4*>(out + (size_t)b * DD);
#pragma unroll
        for (int i = 0; i < 4; i++)
            dst[lane + i * 32] = src[lane + i * 32];
        if (lane == 0) {                       // reset for next graph replay
            g_best[b] = 0ULL;
            __threadfence();
            g_cnt[b] = 0;
        }
    }
}

__global__ __launch_bounds__(256, 3) void knn_pipe_kernel(
    const float* __restrict__ inputs,   // [BB, DD]
    const float* __restrict__ buffer,   // [BB, MM, DD]
    float* __restrict__ out)            // [BB, DD]
{
    const int gw   = blockIdx.x * 8 + (threadIdx.x >> 5);
    const int lane = threadIdx.x & 31;

    // Contiguous row range for this warp (balanced 36/37 rows).
    int r0 = (int)((long long)TOTAL_ROWS * gw / WARPS_TOTAL);
    int r1 = (int)((long long)TOTAL_ROWS * (gw + 1) / WARPS_TOTAL);
    if (r0 >= r1) return;

    int r = r0;
    int b = r >> 11;                    // / MM

    // Query row in registers (reloaded only on batch crossing, <=2x per warp).
    const float4* qp = reinterpret_cast<const float4*>(inputs + (size_t)b * DD);
    float4 q0 = qp[lane], q1 = qp[lane + 32], q2 = qp[lane + 64], q3 = qp[lane + 96];

    // Prime a 2-deep pipeline: rows r and r+1 in flight before first compute.
    const float4* rp = reinterpret_cast<const float4*>(buffer + (size_t)r * DD);
    float4 v0 = __ldg(rp + lane),      v1 = __ldg(rp + lane + 32),
           v2 = __ldg(rp + lane + 64), v3 = __ldg(rp + lane + 96);

    bool   hn = (r + 1 < r1);
    float4 n0, n1, n2, n3;
    if (hn) {
        const float4* np = reinterpret_cast<const float4*>(buffer + (size_t)(r + 1) * DD);
        n0 = __ldg(np + lane);      n1 = __ldg(np + lane + 32);
        n2 = __ldg(np + lane + 64); n3 = __ldg(np + lane + 96);
    }

    float best  = -1.0f;
    int   bestm = 0;
    int   nrows = 0;

    for (;;) {
        // Issue row r+2 BEFORE consuming row r: 8 loads/warp stay in flight
        // through the FMA + shuffle window.
        const bool hp = (r + 2 < r1);
        float4 p0, p1, p2, p3;
        if (hp) {
            const float4* pp = reinterpret_cast<const float4*>(buffer + (size_t)(r + 2) * DD);
            p0 = __ldg(pp + lane);      p1 = __ldg(pp + lane + 32);
            p2 = __ldg(pp + lane + 64); p3 = __ldg(pp + lane + 96);
        }

        float acc = 0.0f;
        {
            float dx = v0.x - q0.x, dy = v0.y - q0.y, dz = v0.z - q0.z, dw = v0.w - q0.w;
            acc = fmaf(dx, dx, acc); acc = fmaf(dy, dy, acc);
            acc = fmaf(dz, dz, acc); acc = fmaf(dw, dw, acc);
            dx = v1.x - q1.x; dy = v1.y - q1.y; dz = v1.z - q1.z; dw = v1.w - q1.w;
            acc = fmaf(dx, dx, acc); acc = fmaf(dy, dy, acc);
            acc = fmaf(dz, dz, acc); acc = fmaf(dw, dw, acc);
            dx = v2.x - q2.x; dy = v2.y - q2.y; dz = v2.z - q2.z; dw = v2.w - q2.w;
            acc = fmaf(dx, dx, acc); acc = fmaf(dy, dy, acc);
            acc = fmaf(dz, dz, acc); acc = fmaf(dw, dw, acc);
            dx = v3.x - q3.x; dy = v3.y - q3.y; dz = v3.z - q3.z; dw = v3.w - q3.w;
            acc = fmaf(dx, dx, acc); acc = fmaf(dy, dy, acc);
            acc = fmaf(dz, dz, acc); acc = fmaf(dw, dw, acc);
        }
#pragma unroll
        for (int o = 16; o > 0; o >>= 1)
            acc += __shfl_xor_sync(0xFFFFFFFFu, acc, o);

        const int m = r & (MM - 1);
        if (acc > best) { best = acc; bestm = m; }
        nrows++;

        if (!hn) {
            flush_batch(b, best, bestm, nrows, lane, buffer, out);
            break;
        }
        const int rn = r + 1;
        const int nb = rn >> 11;
        if (nb != b) {
            flush_batch(b, best, bestm, nrows, lane, buffer, out);
            b = nb;
            qp = reinterpret_cast<const float4*>(inputs + (size_t)b * DD);
            q0 = qp[lane]; q1 = qp[lane + 32]; q2 = qp[lane + 64]; q3 = qp[lane + 96];
            best = -1.0f; bestm = 0; nrows = 0;
        }
        r  = rn;
        v0 = n0; v1 = n1; v2 = n2; v3 = n3;
        n0 = p0; n1 = p1; n2 = p2; n3 = p3;
        hn = hp;
    }
}

extern "C" void kernel_launch(void* const* d_in, const int* in_sizes, int n_in,
                              void* d_out, int out_size)
{
    const float* inputs;
    const float* buffer;
    // inputs has BB*DD = 32768 elems, buffer has BB*MM*DD = 67108864.
    if (in_sizes[0] == BB * DD) {
        inputs = (const float*)d_in[0];
        buffer = (const float*)d_in[1];
    } else {
        inputs = (const float*)d_in[1];
        buffer = (const float*)d_in[0];
    }
    float* out = (float*)d_out;

    knn_pipe_kernel<<<GRID_BLOCKS, 256>>>(inputs, buffer, out);
}